// round 13
// baseline (speedup 1.0000x reference)
#include <cuda_runtime.h>
#include <math.h>

#define NN 100000
#define NE 1600000
#define F  64
#define NC 40

// Scratch (__device__ globals; no cudaMalloc allowed)
__device__ float g_sum[NN * F];     // h + sum_{j in N(i)} h_j
__device__ float g_h[NN * F];       // layer output h
__device__ int   g_deg[NN];
__device__ int   g_rowptr[NN + 1];
__device__ int   g_cursor[NN];
__device__ int   g_csr[NE];         // src indices grouped by dst

// ---------------------------------------------------------------------------
// CSR build: counting sort of edges by dst.  edge_index int32 [2, NE].
// ---------------------------------------------------------------------------
__global__ void zero_deg_kernel() {
    int i = blockIdx.x * blockDim.x + threadIdx.x;
    if (i < NN) g_deg[i] = 0;
}

__global__ void hist_kernel(const int* __restrict__ ei) {
    int e = blockIdx.x * blockDim.x + threadIdx.x;
    if (e >= NE) return;
    int d = ei[NE + e];
    if ((unsigned)d < NN) atomicAdd(&g_deg[d], 1);
}

// Single-block exclusive scan of g_deg -> g_rowptr/g_cursor.
// 1024 threads; thread t serially scans its contiguous 98-element chunk,
// block-level Hillis-Steele combines the partials.
#define CHUNK ((NN + 1023) / 1024)   // 98
__global__ void __launch_bounds__(1024)
scan_kernel() {
    __shared__ int sm[1024];
    int t = threadIdx.x;
    int beg = t * CHUNK;
    int end = min(beg + CHUNK, NN);
    int s = 0;
    for (int i = beg; i < end; i++) s += g_deg[i];
    sm[t] = s;
    __syncthreads();
#pragma unroll
    for (int off = 1; off < 1024; off <<= 1) {
        int v = (t >= off) ? sm[t - off] : 0;
        __syncthreads();
        sm[t] += v;
        __syncthreads();
    }
    int run = sm[t] - s;   // exclusive prefix of this chunk
    for (int i = beg; i < end; i++) {
        int d = g_deg[i];
        g_rowptr[i] = run;
        g_cursor[i] = run;
        run += d;
    }
    if (t == 0) g_rowptr[NN] = NE;
}

__global__ void fill_csr_kernel(const int* __restrict__ ei) {
    int e = blockIdx.x * blockDim.x + threadIdx.x;
    if (e >= NE) return;
    int s = ei[e];
    int d = ei[NE + e];
    if ((unsigned)s >= NN || (unsigned)d >= NN) return;
    int pos = atomicAdd(&g_cursor[d], 1);
    g_csr[pos] = s;
}

// ---------------------------------------------------------------------------
// Pull aggregation: g_sum[i] = h[i] + sum_{j in N(i)} h[src_j].
// ONE WARP PER NODE, two edges per iteration:
//   lanes 0-15 handle edge j (each lane one float4 of the 64-float row),
//   lanes 16-31 handle edge j+1.  No cross-node divergence; one LDG.128
//   issue covers 2 edges (512B).  Halves merged via shfl.xor(16).
// ---------------------------------------------------------------------------
template <bool FROM_H>
__global__ void __launch_bounds__(256)
pull_agg_kernel(const float* __restrict__ feat) {
    int node = (blockIdx.x * blockDim.x + threadIdx.x) >> 5;
    if (node >= NN) return;
    int lane = threadIdx.x & 31;
    int part = lane & 15;     // which float4 of the row
    int half = lane >> 4;     // which edge of the pair
    const float* base = FROM_H ? g_h : feat;

    int beg = g_rowptr[node];
    int end = g_rowptr[node + 1];

    float4 acc = make_float4(0.f, 0.f, 0.f, 0.f);
    for (int jb = beg; jb < end; jb += 2) {
        int e = jb + half;
        if (e < end) {
            int s = __ldg(&g_csr[e]);
            float4 v = ((const float4*)(base + (size_t)s * F))[part];
            acc.x += v.x; acc.y += v.y; acc.z += v.z; acc.w += v.w;
        }
    }
    // merge the two halves
    acc.x += __shfl_xor_sync(0xffffffffu, acc.x, 16);
    acc.y += __shfl_xor_sync(0xffffffffu, acc.y, 16);
    acc.z += __shfl_xor_sync(0xffffffffu, acc.z, 16);
    acc.w += __shfl_xor_sync(0xffffffffu, acc.w, 16);

    if (half == 0) {
        float4 self = ((const float4*)(base + (size_t)node * F))[part];
        acc.x += self.x; acc.y += self.y; acc.z += self.z; acc.w += self.w;
        ((float4*)(g_sum + (size_t)node * F))[part] = acc;
    }
}

// ---------------------------------------------------------------------------
// g_h := relu(g_sum @ W + b).  128 threads, 128 rows/block.
// Thread t: rg = t>>2 (rows rg*4..rg*4+3), q = t&3 (cols q*16..q*16+15).
// Input tile transposed in smem (inT[k][row], pad 132): 5 LDS.128 / 64 FFMA.
// ---------------------------------------------------------------------------
__global__ void __launch_bounds__(128)
gemm64_relu_kernel(const float* __restrict__ W,
                   const float* __restrict__ b) {
    __shared__ float inT[64 * 132];   // [k][row], pad 132
    __shared__ float Wsh[64 * 68];    // [k][col], pad 68
    int t = threadIdx.x;
    int rbase = blockIdx.x * 128;

    for (int i = t; i < 4096; i += 128)
        Wsh[(i >> 6) * 68 + (i & 63)] = W[i];
    for (int i = t; i < 2048; i += 128) {
        int row = i & 127, c4 = i >> 7;
        int gr = rbase + row;
        float4 v = make_float4(0.f, 0.f, 0.f, 0.f);
        if (gr < NN) v = ((const float4*)(g_sum + (size_t)gr * 64))[c4];
        int k0 = c4 * 4;
        inT[(k0 + 0) * 132 + row] = v.x;
        inT[(k0 + 1) * 132 + row] = v.y;
        inT[(k0 + 2) * 132 + row] = v.z;
        inT[(k0 + 3) * 132 + row] = v.w;
    }
    __syncthreads();

    int rg = t >> 2;          // 0..31
    int q  = t & 3;
    int cb = q << 4;

    float acc[4][16];
#pragma unroll
    for (int j = 0; j < 16; j++) {
        float bj = b[cb + j];
#pragma unroll
        for (int r = 0; r < 4; r++) acc[r][j] = bj;
    }

#pragma unroll 8
    for (int k = 0; k < 64; k++) {
        float4 a = *(const float4*)&inT[k * 132 + rg * 4];
        const float4* wp = (const float4*)&Wsh[k * 68 + cb];
        float4 w0 = wp[0], w1 = wp[1], w2 = wp[2], w3 = wp[3];
        const float wv[16] = {w0.x, w0.y, w0.z, w0.w, w1.x, w1.y, w1.z, w1.w,
                              w2.x, w2.y, w2.z, w2.w, w3.x, w3.y, w3.z, w3.w};
        const float av[4] = {a.x, a.y, a.z, a.w};
#pragma unroll
        for (int r = 0; r < 4; r++)
#pragma unroll
            for (int j = 0; j < 16; j++)
                acc[r][j] = fmaf(av[r], wv[j], acc[r][j]);
    }

#pragma unroll
    for (int r = 0; r < 4; r++) {
        int gr = rbase + rg * 4 + r;
        if (gr < NN) {
            float4* o = (float4*)(g_h + (size_t)gr * 64 + cb);
#pragma unroll
            for (int v4i = 0; v4i < 4; v4i++) {
                float4 ov;
                ov.x = fmaxf(acc[r][v4i * 4 + 0], 0.f);
                ov.y = fmaxf(acc[r][v4i * 4 + 1], 0.f);
                ov.z = fmaxf(acc[r][v4i * 4 + 2], 0.f);
                ov.w = fmaxf(acc[r][v4i * 4 + 3], 0.f);
                o[v4i] = ov;
            }
        }
    }
}

// ---------------------------------------------------------------------------
// logits = g_h @ Wf + bf; out = log_softmax(logits).  One warp per row.
// ---------------------------------------------------------------------------
__global__ void __launch_bounds__(256)
final_logsoftmax_kernel(const float* __restrict__ Wf,
                        const float* __restrict__ bf,
                        float* __restrict__ out,
                        int n) {
    __shared__ float Wfs[64 * NC];
    __shared__ float bfs[NC];
    __shared__ float hs[8][64];
    int t = threadIdx.x;
    for (int i = t; i < 64 * NC; i += 256) Wfs[i] = Wf[i];
    if (t < NC) bfs[t] = bf[t];

    int warp = t >> 5, lane = t & 31;
    int row = blockIdx.x * 8 + warp;
    if (row < n) {
        hs[warp][lane]      = g_h[(size_t)row * 64 + lane];
        hs[warp][lane + 32] = g_h[(size_t)row * 64 + lane + 32];
    }
    __syncthreads();
    if (row >= n) return;

    int c1 = 32 + lane;
    bool has1 = (c1 < NC);
    int idx1 = has1 ? c1 : 0;

    float acc0 = bfs[lane];
    float acc1 = has1 ? bfs[idx1] : 0.f;
#pragma unroll
    for (int k = 0; k < 64; k++) {
        float hk = hs[warp][k];
        acc0 = fmaf(hk, Wfs[k * NC + lane], acc0);
        acc1 = fmaf(hk, Wfs[k * NC + idx1], acc1);
    }

    float m = acc0;
    if (has1) m = fmaxf(m, acc1);
#pragma unroll
    for (int o = 16; o; o >>= 1) m = fmaxf(m, __shfl_xor_sync(0xffffffffu, m, o));
    float s = expf(acc0 - m) + (has1 ? expf(acc1 - m) : 0.f);
#pragma unroll
    for (int o = 16; o; o >>= 1) s += __shfl_xor_sync(0xffffffffu, s, o);
    float lse = m + logf(s);

    out[(size_t)row * NC + lane] = acc0 - lse;
    if (has1) out[(size_t)row * NC + c1] = acc1 - lse;
}

// ---------------------------------------------------------------------------
extern "C" void kernel_launch(void* const* d_in, const int* in_sizes, int n_in,
                              void* d_out, int out_size) {
    const float* x  = (const float*)d_in[0];
    const int*   ei = (const int*)d_in[1];
    const float* W1 = (const float*)d_in[2];
    const float* b1 = (const float*)d_in[3];
    const float* W2 = (const float*)d_in[4];
    const float* b2 = (const float*)d_in[5];
    const float* Wf = (const float*)d_in[6];
    const float* bf = (const float*)d_in[7];
    float*       out = (float*)d_out;

    const int nn_blocks   = (NN + 255) / 256;        // 391
    const int ne_blocks   = (NE + 255) / 256;        // 6250
    const int pull_blocks = (NN * 32 + 255) / 256;   // 12500 (1 warp/node)
    const int gemm_blocks = (NN + 127) / 128;        // 782
    const int fin_blocks  = (NN + 7) / 8;            // 12500

    // CSR build (once; reused by both layers)
    zero_deg_kernel<<<nn_blocks, 256>>>();
    hist_kernel<<<ne_blocks, 256>>>(ei);
    scan_kernel<<<1, 1024>>>();
    fill_csr_kernel<<<ne_blocks, 256>>>(ei);

    // Layer 1
    pull_agg_kernel<false><<<pull_blocks, 256>>>(x);
    gemm64_relu_kernel<<<gemm_blocks, 128>>>(W1, b1);
    // Layer 2
    pull_agg_kernel<true><<<pull_blocks, 256>>>(nullptr);
    gemm64_relu_kernel<<<gemm_blocks, 128>>>(W2, b2);
    // Classifier + log_softmax
    final_logsoftmax_kernel<<<fin_blocks, 256>>>(Wf, bf, out, NN);
}